// round 1
// baseline (speedup 1.0000x reference)
#include <cuda_runtime.h>
#include <math.h>

// ---------------- problem constants ----------------
namespace cfg {
constexpr int B = 2, T = 2048, D = 1024, H = 16, HD = 64, F = 4096, V = 32000;
constexpr int M = B * T;  // 4096 token rows
constexpr float EPS = 1e-6f;
}

// ---------------- scratch (static device arrays; no allocs allowed) --------
__device__ float g_h[cfg::M * cfg::D];
__device__ float g_q[cfg::M * cfg::D];
__device__ float g_k[cfg::M * cfg::D];
__device__ float g_v[cfg::M * cfg::D];
__device__ float g_o[cfg::M * cfg::D];
__device__ float g_f[(size_t)cfg::M * cfg::F];

// ---------------- embed + sinusoidal positional encoding -------------------
__global__ void embed_kernel(const int* __restrict__ x, const float* __restrict__ emb,
                             float* __restrict__ h) {
    int row = blockIdx.x;                 // 0..M-1 = b*T + t
    int t = row & (cfg::T - 1);
    int tok = x[row];
    const float* e = emb + (size_t)tok * cfg::D;
    float* out = h + (size_t)row * cfg::D;

    int d0 = threadIdx.x * 4;             // 256 threads * 4 = 1024 = D
    float4 ev = *(const float4*)&e[d0];
    // exponent factor: -2*ln(10000)/D
    const float cfac = -0.017988946039015984f;
    int i0 = d0 >> 1;
    float f0 = expf((float)i0 * cfac);
    float f1 = expf((float)(i0 + 1) * cfac);
    float a0 = (float)t * f0;
    float a1 = (float)t * f1;
    float4 o;
    o.x = ev.x + sinf(a0);
    o.y = ev.y + cosf(a0);
    o.z = ev.z + sinf(a1);
    o.w = ev.w + cosf(a1);
    *(float4*)&out[d0] = o;
}

// ---------------- tiled SGEMM: C = A[MxK] @ B[KxN] + bias (+ReLU) ----------
// 128x128 tile, BK=16, 256 threads, 8x8 per thread (split 4+4 halves).
template <bool RELU>
__global__ __launch_bounds__(256) void sgemm_kernel(
    const float* __restrict__ A, const float* __restrict__ Bm,
    const float* __restrict__ bias, float* __restrict__ C,
    int Md, int Nd, int Kd) {
    __shared__ float As[16 * 128];  // As[k][m]
    __shared__ float Bs[16 * 128];  // Bs[k][n]

    const int bm = blockIdx.y * 128;
    const int bn = blockIdx.x * 128;
    const int tid = threadIdx.x;
    const int tx4 = (tid & 15) * 4;
    const int ty4 = (tid >> 4) * 4;

    float acc[8][8];
#pragma unroll
    for (int i = 0; i < 8; i++)
#pragma unroll
        for (int j = 0; j < 8; j++) acc[i][j] = 0.f;

    for (int k0 = 0; k0 < Kd; k0 += 16) {
        // load A tile (128 rows x 16 k), store transposed As[k][m]
#pragma unroll
        for (int it = 0; it < 2; it++) {
            int idx = tid + it * 256;          // 0..511 float4 slots
            int mrow = idx >> 2;               // 0..127
            int kq = (idx & 3) * 4;            // 0,4,8,12
            float4 t = *(const float4*)&A[(size_t)(bm + mrow) * Kd + k0 + kq];
            As[(kq + 0) * 128 + mrow] = t.x;
            As[(kq + 1) * 128 + mrow] = t.y;
            As[(kq + 2) * 128 + mrow] = t.z;
            As[(kq + 3) * 128 + mrow] = t.w;
        }
        // load B tile (16 k x 128 n), natural layout
#pragma unroll
        for (int it = 0; it < 2; it++) {
            int idx = tid + it * 256;
            int krow = idx >> 5;               // 0..15
            int nq = (idx & 31) * 4;           // 0..124
            *(float4*)&Bs[krow * 128 + nq] =
                *(const float4*)&Bm[(size_t)(k0 + krow) * Nd + bn + nq];
        }
        __syncthreads();

#pragma unroll
        for (int kk = 0; kk < 16; kk++) {
            float a[8], b[8];
            *(float4*)&a[0] = *(float4*)&As[kk * 128 + ty4];
            *(float4*)&a[4] = *(float4*)&As[kk * 128 + 64 + ty4];
            *(float4*)&b[0] = *(float4*)&Bs[kk * 128 + tx4];
            *(float4*)&b[4] = *(float4*)&Bs[kk * 128 + 64 + tx4];
#pragma unroll
            for (int i = 0; i < 8; i++)
#pragma unroll
                for (int j = 0; j < 8; j++) acc[i][j] += a[i] * b[j];
        }
        __syncthreads();
    }

    // epilogue
#pragma unroll
    for (int i = 0; i < 8; i++) {
        int mrow = bm + ((i < 4) ? (ty4 + i) : (64 + ty4 + (i - 4)));
#pragma unroll
        for (int jh = 0; jh < 2; jh++) {
            int ncol = bn + jh * 64 + tx4;
            float4 r;
            r.x = acc[i][jh * 4 + 0] + bias[ncol + 0];
            r.y = acc[i][jh * 4 + 1] + bias[ncol + 1];
            r.z = acc[i][jh * 4 + 2] + bias[ncol + 2];
            r.w = acc[i][jh * 4 + 3] + bias[ncol + 3];
            if (RELU) {
                r.x = fmaxf(r.x, 0.f); r.y = fmaxf(r.y, 0.f);
                r.z = fmaxf(r.z, 0.f); r.w = fmaxf(r.w, 0.f);
            }
            *(float4*)&C[(size_t)mrow * Nd + ncol] = r;
        }
    }
}

// ---------------- flash attention (fp32, 64x64 tiles, causal) --------------
// q,k,v,o: [B,T,D] row-major; head h occupies cols [h*64, h*64+64).
__global__ __launch_bounds__(256) void flash_kernel(
    const float* __restrict__ q, const float* __restrict__ k,
    const float* __restrict__ v, float* __restrict__ o) {
    __shared__ float Qt[64 * 64];   // [d][i]
    __shared__ float KVs[64 * 64];  // K phase: [d][j]; V phase: [j][d]
    __shared__ float Ps[64 * 64];   // [i][j]

    const int qi = blockIdx.x;      // q tile
    const int h = blockIdx.y;
    const int b = blockIdx.z;
    const int tid = threadIdx.x;
    const int tx4 = (tid & 15) * 4;
    const int ty4 = (tid >> 4) * 4;
    const size_t headoff = ((size_t)b * cfg::T) * cfg::D + (size_t)h * cfg::HD;
    const float scale = 0.125f;     // 1/sqrt(64)

    // load Q tile transposed
#pragma unroll
    for (int it = 0; it < 4; it++) {
        int idx = tid + it * 256;          // 1024 float4 slots
        int r = idx >> 4;                  // 0..63 row
        int dq = (idx & 15) * 4;           // 0..60
        float4 t = *(const float4*)&q[headoff + (size_t)(qi * 64 + r) * cfg::D + dq];
        Qt[(dq + 0) * 64 + r] = t.x;
        Qt[(dq + 1) * 64 + r] = t.y;
        Qt[(dq + 2) * 64 + r] = t.z;
        Qt[(dq + 3) * 64 + r] = t.w;
    }

    float m_i[4], l_i[4], acc[4][4];
#pragma unroll
    for (int i = 0; i < 4; i++) {
        m_i[i] = -1e30f; l_i[i] = 0.f;
#pragma unroll
        for (int j = 0; j < 4; j++) acc[i][j] = 0.f;
    }

    for (int kt = 0; kt <= qi; kt++) {
        // load K tile transposed into KVs
#pragma unroll
        for (int it = 0; it < 4; it++) {
            int idx = tid + it * 256;
            int r = idx >> 4;
            int dq = (idx & 15) * 4;
            float4 t = *(const float4*)&k[headoff + (size_t)(kt * 64 + r) * cfg::D + dq];
            KVs[(dq + 0) * 64 + r] = t.x;
            KVs[(dq + 1) * 64 + r] = t.y;
            KVs[(dq + 2) * 64 + r] = t.z;
            KVs[(dq + 3) * 64 + r] = t.w;
        }
        __syncthreads();  // Q (first iter) + K ready; prev-iter Ps reads done

        // S = Q @ K^T (this thread: rows ty4+i, cols tx4+j)
        float s[4][4];
#pragma unroll
        for (int i = 0; i < 4; i++)
#pragma unroll
            for (int j = 0; j < 4; j++) s[i][j] = 0.f;
#pragma unroll 8
        for (int d = 0; d < 64; d++) {
            float a[4], bb[4];
            *(float4*)a = *(float4*)&Qt[d * 64 + ty4];
            *(float4*)bb = *(float4*)&KVs[d * 64 + tx4];
#pragma unroll
            for (int i = 0; i < 4; i++)
#pragma unroll
                for (int j = 0; j < 4; j++) s[i][j] += a[i] * bb[j];
        }

        // scale + causal mask (only diagonal tile needs masking)
        const bool diag = (kt == qi);
        float mt[4];
#pragma unroll
        for (int i = 0; i < 4; i++) {
            mt[i] = -1e30f;
#pragma unroll
            for (int j = 0; j < 4; j++) {
                float sv = s[i][j] * scale;
                if (diag && (tx4 + j) > (ty4 + i)) sv = -1e30f;
                s[i][j] = sv;
                mt[i] = fmaxf(mt[i], sv);
            }
        }
        // row max across the 16 lanes sharing these rows (half-warp butterfly)
#pragma unroll
        for (int i = 0; i < 4; i++)
#pragma unroll
            for (int off = 8; off; off >>= 1)
                mt[i] = fmaxf(mt[i], __shfl_xor_sync(0xffffffffu, mt[i], off));

        float alpha[4], rs[4];
#pragma unroll
        for (int i = 0; i < 4; i++) {
            float mnew = fmaxf(m_i[i], mt[i]);
            alpha[i] = expf(m_i[i] - mnew);
            m_i[i] = mnew;
            rs[i] = 0.f;
#pragma unroll
            for (int j = 0; j < 4; j++) {
                float p = expf(s[i][j] - mnew);
                s[i][j] = p;
                rs[i] += p;
            }
        }
#pragma unroll
        for (int i = 0; i < 4; i++)
#pragma unroll
            for (int off = 8; off; off >>= 1)
                rs[i] += __shfl_xor_sync(0xffffffffu, rs[i], off);
#pragma unroll
        for (int i = 0; i < 4; i++) {
            l_i[i] = l_i[i] * alpha[i] + rs[i];
#pragma unroll
            for (int j = 0; j < 4; j++) acc[i][j] *= alpha[i];
        }

        // write P tile [i][j]
#pragma unroll
        for (int i = 0; i < 4; i++)
            *(float4*)&Ps[(ty4 + i) * 64 + tx4] = *(float4*)&s[i][0];
        __syncthreads();  // all done reading K from KVs; P visible

        // load V tile (natural layout) into KVs
#pragma unroll
        for (int it = 0; it < 4; it++) {
            int idx = tid + it * 256;
            int r = idx >> 4;
            int dq = (idx & 15) * 4;
            *(float4*)&KVs[r * 64 + dq] =
                *(const float4*)&v[headoff + (size_t)(kt * 64 + r) * cfg::D + dq];
        }
        __syncthreads();

        // O += P @ V   (rows ty4+i, dcols tx4+x)
#pragma unroll 4
        for (int jj = 0; jj < 64; jj += 4) {
            float a[4][4];
#pragma unroll
            for (int i = 0; i < 4; i++)
                *(float4*)a[i] = *(float4*)&Ps[(ty4 + i) * 64 + jj];
#pragma unroll
            for (int c = 0; c < 4; c++) {
                float bb[4];
                *(float4*)bb = *(float4*)&KVs[(jj + c) * 64 + tx4];
#pragma unroll
                for (int i = 0; i < 4; i++)
#pragma unroll
                    for (int xcol = 0; xcol < 4; xcol++)
                        acc[i][xcol] += a[i][c] * bb[xcol];
            }
        }
        __syncthreads();  // before next K load / P rewrite
    }

    // write O = acc / l
#pragma unroll
    for (int i = 0; i < 4; i++) {
        float inv = 1.0f / l_i[i];
        int row = qi * 64 + ty4 + i;
        float4 r;
        r.x = acc[i][0] * inv; r.y = acc[i][1] * inv;
        r.z = acc[i][2] * inv; r.w = acc[i][3] * inv;
        *(float4*)&o[headoff + (size_t)row * cfg::D + tx4] = r;
    }
}

// ---------------- layernorm (unbiased std, torch semantics) ----------------
__inline__ __device__ float block_reduce_sum(float val) {
    __shared__ float sbuf[8];
    int lane = threadIdx.x & 31, wid = threadIdx.x >> 5;
#pragma unroll
    for (int o = 16; o; o >>= 1) val += __shfl_xor_sync(0xffffffffu, val, o);
    if (lane == 0) sbuf[wid] = val;
    __syncthreads();
    val = (threadIdx.x < 8) ? sbuf[threadIdx.x] : 0.f;
    if (wid == 0) {
#pragma unroll
        for (int o = 4; o; o >>= 1) val += __shfl_xor_sync(0xffffffffu, val, o);
        if (lane == 0) sbuf[0] = val;
    }
    __syncthreads();
    float r = sbuf[0];
    __syncthreads();  // protect sbuf for a second call
    return r;
}

__global__ void layernorm_kernel(float* __restrict__ h, const float* __restrict__ g,
                                 const float* __restrict__ be) {
    int row = blockIdx.x;
    float* p = h + (size_t)row * cfg::D;
    int d0 = threadIdx.x * 4;
    float4 xv = *(float4*)&p[d0];
    float s = xv.x + xv.y + xv.z + xv.w;
    s = block_reduce_sum(s);
    float mean = s * (1.0f / cfg::D);
    float dx[4] = {xv.x - mean, xv.y - mean, xv.z - mean, xv.w - mean};
    float sq = dx[0] * dx[0] + dx[1] * dx[1] + dx[2] * dx[2] + dx[3] * dx[3];
    sq = block_reduce_sum(sq);
    float stdv = sqrtf(sq / (float)(cfg::D - 1));   // ddof=1
    float inv = 1.0f / (stdv + cfg::EPS);
    float4 gg = *(const float4*)&g[d0];
    float4 bb = *(const float4*)&be[d0];
    float4 o;
    o.x = dx[0] * inv * gg.x + bb.x;
    o.y = dx[1] * inv * gg.y + bb.y;
    o.z = dx[2] * inv * gg.z + bb.z;
    o.w = dx[3] * inv * gg.w + bb.w;
    *(float4*)&p[d0] = o;
}

// ---------------- row softmax over V=32000 (in-place on d_out) -------------
__global__ void softmax_kernel(float* __restrict__ out) {
    int row = blockIdx.x;
    float* p = out + (size_t)row * cfg::V;
    float m = -1e30f, s = 0.f;
    for (int j = threadIdx.x; j < cfg::V; j += 256) {
        float xv = p[j];
        if (xv > m) { s = s * expf(m - xv) + 1.0f; m = xv; }
        else        { s += expf(xv - m); }
    }
    __shared__ float sm[256], ss[256];
    sm[threadIdx.x] = m; ss[threadIdx.x] = s;
    __syncthreads();
    for (int off = 128; off; off >>= 1) {
        if (threadIdx.x < off) {
            float m1 = sm[threadIdx.x], s1 = ss[threadIdx.x];
            float m2 = sm[threadIdx.x + off], s2 = ss[threadIdx.x + off];
            float mm = fmaxf(m1, m2);
            sm[threadIdx.x] = mm;
            ss[threadIdx.x] = s1 * expf(m1 - mm) + s2 * expf(m2 - mm);
        }
        __syncthreads();
    }
    float mall = sm[0];
    float inv = 1.0f / ss[0];
    for (int j = threadIdx.x; j < cfg::V; j += 256) {
        p[j] = expf(p[j] - mall) * inv;
    }
}

// ---------------- host orchestration ---------------------------------------
extern "C" void kernel_launch(void* const* d_in, const int* in_sizes, int n_in,
                              void* d_out, int out_size) {
    using namespace cfg;
    const int*   x   = (const int*)d_in[0];
    const float* emb = (const float*)d_in[1];
    const float* Wq  = (const float*)d_in[2];
    const float* bq  = (const float*)d_in[3];
    const float* Wk  = (const float*)d_in[4];
    const float* bk  = (const float*)d_in[5];
    const float* Wv  = (const float*)d_in[6];
    const float* bv  = (const float*)d_in[7];
    const float* Wo  = (const float*)d_in[8];
    const float* bo  = (const float*)d_in[9];
    const float* g1  = (const float*)d_in[10];
    const float* be1 = (const float*)d_in[11];
    const float* W1  = (const float*)d_in[12];
    const float* bf1 = (const float*)d_in[13];
    const float* W2  = (const float*)d_in[14];
    const float* bf2 = (const float*)d_in[15];
    const float* g2  = (const float*)d_in[16];
    const float* be2 = (const float*)d_in[17];
    const float* Wl  = (const float*)d_in[18];
    const float* bl  = (const float*)d_in[19];
    float* out = (float*)d_out;

    float *h, *q, *k, *v, *o, *f;
    cudaGetSymbolAddress((void**)&h, g_h);
    cudaGetSymbolAddress((void**)&q, g_q);
    cudaGetSymbolAddress((void**)&k, g_k);
    cudaGetSymbolAddress((void**)&v, g_v);
    cudaGetSymbolAddress((void**)&o, g_o);
    cudaGetSymbolAddress((void**)&f, g_f);

    embed_kernel<<<M, 256>>>(x, emb, h);

    sgemm_kernel<false><<<dim3(D / 128, M / 128), 256>>>(h, Wq, bq, q, M, D, D);
    sgemm_kernel<false><<<dim3(D / 128, M / 128), 256>>>(h, Wk, bk, k, M, D, D);
    sgemm_kernel<false><<<dim3(D / 128, M / 128), 256>>>(h, Wv, bv, v, M, D, D);

    flash_kernel<<<dim3(T / 64, H, B), 256>>>(q, k, v, o);

    sgemm_kernel<false><<<dim3(D / 128, M / 128), 256>>>(o, Wo, bo, h, M, D, D);
    layernorm_kernel<<<M, 256>>>(h, g1, be1);

    sgemm_kernel<true><<<dim3(F / 128, M / 128), 256>>>(h, W1, bf1, f, M, F, D);
    sgemm_kernel<false><<<dim3(D / 128, M / 128), 256>>>(f, W2, bf2, o, M, D, F);
    layernorm_kernel<<<M, 256>>>(o, g2, be2);

    sgemm_kernel<false><<<dim3(V / 128, M / 128), 256>>>(o, Wl, bl, out, M, V, D);
    softmax_kernel<<<M, 256>>>(out);
}

// round 3
// speedup vs baseline: 1.7184x; 1.7184x over previous
#include <cuda_runtime.h>
#include <cuda_bf16.h>
#include <math.h>
#include <stdint.h>

// ---------------- problem constants ----------------
namespace cfg {
constexpr int B = 2, T = 2048, D = 1024, H = 16, HD = 64, F = 4096, V = 32000;
constexpr int M = B * T;  // 4096 token rows
constexpr float EPS = 1e-6f;
}

// ---------------- scratch (static device arrays; no allocs allowed) --------
__device__ float g_h[cfg::M * cfg::D];
__device__ float g_q[cfg::M * cfg::D];
__device__ float g_k[cfg::M * cfg::D];
__device__ float g_v[cfg::M * cfg::D];
__device__ float g_o[cfg::M * cfg::D];
__device__ float g_f[(size_t)cfg::M * cfg::F];

// bf16 split buffers: activations (hi/lo) and transposed-split weights
__device__ __nv_bfloat16 g_ah[(size_t)cfg::M * cfg::F];
__device__ __nv_bfloat16 g_al[(size_t)cfg::M * cfg::F];
__device__ __nv_bfloat16 g_wqh[cfg::D * cfg::D], g_wql[cfg::D * cfg::D];
__device__ __nv_bfloat16 g_wkh[cfg::D * cfg::D], g_wkl[cfg::D * cfg::D];
__device__ __nv_bfloat16 g_wvh[cfg::D * cfg::D], g_wvl[cfg::D * cfg::D];
__device__ __nv_bfloat16 g_woh[cfg::D * cfg::D], g_wol[cfg::D * cfg::D];
__device__ __nv_bfloat16 g_w1h[(size_t)cfg::D * cfg::F], g_w1l[(size_t)cfg::D * cfg::F];
__device__ __nv_bfloat16 g_w2h[(size_t)cfg::D * cfg::F], g_w2l[(size_t)cfg::D * cfg::F];
__device__ __nv_bfloat16 g_wlh[(size_t)cfg::V * cfg::D], g_wll[(size_t)cfg::V * cfg::D];

// ---------------- PTX helpers ----------------------------------------------
__device__ __forceinline__ uint32_t smem_u32(const void* p) {
    uint32_t a;
    asm("{ .reg .u64 t; cvta.to.shared.u64 t, %1; cvt.u32.u64 %0, t; }" : "=r"(a) : "l"(p));
    return a;
}
__device__ __forceinline__ void cp16(uint32_t dst, const void* src) {
    asm volatile("cp.async.cg.shared.global [%0], [%1], 16;" :: "r"(dst), "l"(src));
}
__device__ __forceinline__ void cp_commit() {
    asm volatile("cp.async.commit_group;" ::: "memory");
}
template <int N>
__device__ __forceinline__ void cp_wait() {
    asm volatile("cp.async.wait_group %0;" :: "n"(N) : "memory");
}
__device__ __forceinline__ void ldmat4(uint32_t* r, uint32_t addr) {
    asm volatile("ldmatrix.sync.aligned.m8n8.x4.shared.b16 {%0,%1,%2,%3}, [%4];"
                 : "=r"(r[0]), "=r"(r[1]), "=r"(r[2]), "=r"(r[3]) : "r"(addr));
}
__device__ __forceinline__ void mma16816(float* c, const uint32_t* a, uint32_t b0, uint32_t b1) {
    asm volatile(
        "mma.sync.aligned.m16n8k16.row.col.f32.bf16.bf16.f32 "
        "{%0,%1,%2,%3}, {%4,%5,%6,%7}, {%8,%9}, {%0,%1,%2,%3};"
        : "+f"(c[0]), "+f"(c[1]), "+f"(c[2]), "+f"(c[3])
        : "r"(a[0]), "r"(a[1]), "r"(a[2]), "r"(a[3]), "r"(b0), "r"(b1));
}

// ---------------- bf16x3 GEMM on HMMA (mma.sync) ----------------------------
// C[M,N] = A[M,K] @ B^T (+bias, opt ReLU). A,B split hi/lo bf16; B is [N,K].
// CTA tile 128x256, BK=32, 512 threads (16 warps: 2(M) x 8(N), warp 64x32).
// 4-stage cp.async pipeline. Segments: Ah*Bh, Ah*Bl, Al*Bh (K-extended loop).
static constexpr int GSTRIDE = 40;                 // smem row stride in bf16 (80B)
static constexpr uint32_t A_BYTES = 128 * GSTRIDE * 2;   // 10240
static constexpr uint32_t B_BYTES = 256 * GSTRIDE * 2;   // 20480
static constexpr uint32_t STAGE_BYTES = A_BYTES + B_BYTES;  // 30720
static constexpr uint32_t GEMM_SMEM = 4 * STAGE_BYTES;      // 122880

template <bool RELU>
__global__ __launch_bounds__(512, 1) void gemm_hmma(
    const __nv_bfloat16* __restrict__ Ah, const __nv_bfloat16* __restrict__ Al,
    const __nv_bfloat16* __restrict__ Bh, const __nv_bfloat16* __restrict__ Bl,
    const float* __restrict__ bias, float* __restrict__ C, int Nd, int Kd) {
    extern __shared__ char smem[];
    const uint32_t sb = smem_u32(smem);
    const int tid = threadIdx.x;
    const int wid = tid >> 5, lane = tid & 31;
    const int wm = wid & 1, wn = wid >> 1;          // warp coords: 2 x 8
    const int bm = blockIdx.x * 128;
    const int bn = blockIdx.y * 256;

    const int nk = Kd >> 5;        // 32-wide K chunks per segment
    const int NC = 3 * nk;

    // per-thread load slots
    const int arow = tid >> 2, aseg = tid & 3;      // A: 128 rows x 4 segs
    // load cursor
    int lseg = 0, lk = 0;
    const __nv_bfloat16* Asrc[3] = {Ah, Ah, Al};
    const __nv_bfloat16* Bsrc[3] = {Bh, Bl, Bh};

    auto issue_chunk = [&](int stage) {
        const __nv_bfloat16* As = Asrc[lseg];
        const __nv_bfloat16* Bs = Bsrc[lseg];
        uint32_t sA = sb + stage * STAGE_BYTES;
        uint32_t sB = sA + A_BYTES;
        cp16(sA + arow * 80 + aseg * 16,
             As + (size_t)(bm + arow) * Kd + lk + aseg * 8);
#pragma unroll
        for (int it = 0; it < 2; it++) {
            int i = tid + it * 512;
            int br = i >> 2, bs = i & 3;
            cp16(sB + br * 80 + bs * 16,
                 Bs + (size_t)(bn + br) * Kd + lk + bs * 8);
        }
        lk += 32;
        if (lk == Kd) { lk = 0; lseg++; }
    };

    // prologue: 3 chunks in flight
    issue_chunk(0); cp_commit();
    issue_chunk(1); cp_commit();
    issue_chunk(2); cp_commit();

    float acc[4][4][4];
#pragma unroll
    for (int i = 0; i < 4; i++)
#pragma unroll
        for (int j = 0; j < 4; j++)
#pragma unroll
            for (int r = 0; r < 4; r++) acc[i][j][r] = 0.f;

    // precomputed intra-warp ldmatrix offsets
    const int a_r = lane & 15;                  // row within m16
    const int a_c = (lane >> 4) << 3;           // 0 or 8 (k)
    const int b_r = (lane & 7) + ((lane >> 4) << 3);   // row within n16
    const int b_c = ((lane >> 3) & 1) << 3;     // 0 or 8 (k)

    for (int c = 0; c < NC; c++) {
        cp_wait<2>();
        __syncthreads();
        if (c + 3 < NC) issue_chunk((c + 3) & 3);
        cp_commit();

        const uint32_t sA = sb + (c & 3) * STAGE_BYTES;
        const uint32_t sB = sA + A_BYTES;
#pragma unroll
        for (int kk = 0; kk < 2; kk++) {
            uint32_t a[4][4];
#pragma unroll
            for (int mt = 0; mt < 4; mt++) {
                uint32_t addr = sA + (uint32_t)(wm * 64 + mt * 16 + a_r) * 80
                              + (uint32_t)(kk * 16 + a_c) * 2;
                ldmat4(a[mt], addr);
            }
            uint32_t b[2][4];
#pragma unroll
            for (int g = 0; g < 2; g++) {
                uint32_t addr = sB + (uint32_t)(wn * 32 + g * 16 + b_r) * 80
                              + (uint32_t)(kk * 16 + b_c) * 2;
                ldmat4(b[g], addr);
            }
#pragma unroll
            for (int mt = 0; mt < 4; mt++)
#pragma unroll
                for (int nt = 0; nt < 4; nt++) {
                    uint32_t b0 = b[nt >> 1][(nt & 1) * 2 + 0];
                    uint32_t b1 = b[nt >> 1][(nt & 1) * 2 + 1];
                    mma16816(acc[mt][nt], a[mt], b0, b1);
                }
        }
    }

    // epilogue: bias (+ReLU) and store
    const int g = lane >> 2, t = lane & 3;
#pragma unroll
    for (int mt = 0; mt < 4; mt++) {
#pragma unroll
        for (int nt = 0; nt < 4; nt++) {
            int row0 = bm + wm * 64 + mt * 16 + g;
            int col = bn + wn * 32 + nt * 8 + t * 2;
            float bx = bias[col], by = bias[col + 1];
            float2 v0, v1;
            v0.x = acc[mt][nt][0] + bx; v0.y = acc[mt][nt][1] + by;
            v1.x = acc[mt][nt][2] + bx; v1.y = acc[mt][nt][3] + by;
            if (RELU) {
                v0.x = fmaxf(v0.x, 0.f); v0.y = fmaxf(v0.y, 0.f);
                v1.x = fmaxf(v1.x, 0.f); v1.y = fmaxf(v1.y, 0.f);
            }
            *(float2*)&C[(size_t)row0 * Nd + col] = v0;
            *(float2*)&C[(size_t)(row0 + 8) * Nd + col] = v1;
        }
    }
}

// ---------------- split fp32 -> bf16 hi/lo ----------------------------------
__global__ void split_kernel(const float* __restrict__ x, __nv_bfloat16* __restrict__ hi,
                             __nv_bfloat16* __restrict__ lo, int n4) {
    int i = blockIdx.x * blockDim.x + threadIdx.x;
    if (i >= n4) return;
    float4 v = ((const float4*)x)[i];
    __nv_bfloat16 h0 = __float2bfloat16_rn(v.x);
    __nv_bfloat16 h1 = __float2bfloat16_rn(v.y);
    __nv_bfloat16 h2 = __float2bfloat16_rn(v.z);
    __nv_bfloat16 h3 = __float2bfloat16_rn(v.w);
    ((__nv_bfloat162*)hi)[i * 2 + 0] = __halves2bfloat162(h0, h1);
    ((__nv_bfloat162*)hi)[i * 2 + 1] = __halves2bfloat162(h2, h3);
    __nv_bfloat16 l0 = __float2bfloat16_rn(v.x - __bfloat162float(h0));
    __nv_bfloat16 l1 = __float2bfloat16_rn(v.y - __bfloat162float(h1));
    __nv_bfloat16 l2 = __float2bfloat16_rn(v.z - __bfloat162float(h2));
    __nv_bfloat16 l3 = __float2bfloat16_rn(v.w - __bfloat162float(h3));
    ((__nv_bfloat162*)lo)[i * 2 + 0] = __halves2bfloat162(l0, l1);
    ((__nv_bfloat162*)lo)[i * 2 + 1] = __halves2bfloat162(l2, l3);
}

// ---------------- transpose + split weight: W[K,N] -> hi/lo [N,K] -----------
__global__ void tsplit_kernel(const float* __restrict__ W, __nv_bfloat16* __restrict__ hi,
                              __nv_bfloat16* __restrict__ lo, int K, int N) {
    __shared__ float s[32][33];
    int n = blockIdx.x * 32 + threadIdx.x;
    int k = blockIdx.y * 32 + threadIdx.y;
    s[threadIdx.y][threadIdx.x] = W[(size_t)k * N + n];
    __syncthreads();
    int no = blockIdx.x * 32 + threadIdx.y;
    int ko = blockIdx.y * 32 + threadIdx.x;
    float v = s[threadIdx.x][threadIdx.y];
    __nv_bfloat16 h = __float2bfloat16_rn(v);
    hi[(size_t)no * K + ko] = h;
    lo[(size_t)no * K + ko] = __float2bfloat16_rn(v - __bfloat162float(h));
}

// ---------------- embed + sinusoidal positional encoding -------------------
__global__ void embed_kernel(const int* __restrict__ x, const float* __restrict__ emb,
                             float* __restrict__ h) {
    int row = blockIdx.x;
    int t = row & (cfg::T - 1);
    int tok = x[row];
    const float* e = emb + (size_t)tok * cfg::D;
    float* out = h + (size_t)row * cfg::D;
    int d0 = threadIdx.x * 4;
    float4 ev = *(const float4*)&e[d0];
    const float cfac = -0.017988946039015984f;
    int i0 = d0 >> 1;
    float f0 = expf((float)i0 * cfac);
    float f1 = expf((float)(i0 + 1) * cfac);
    float a0 = (float)t * f0, a1 = (float)t * f1;
    float4 o;
    o.x = ev.x + sinf(a0);
    o.y = ev.y + cosf(a0);
    o.z = ev.z + sinf(a1);
    o.w = ev.w + cosf(a1);
    *(float4*)&out[d0] = o;
}

// ---------------- flash attention (fp32, 64x64 tiles, causal) --------------
__global__ __launch_bounds__(256) void flash_kernel(
    const float* __restrict__ q, const float* __restrict__ k,
    const float* __restrict__ v, float* __restrict__ o) {
    __shared__ float Qt[64 * 64];
    __shared__ float KVs[64 * 64];
    __shared__ float Ps[64 * 64];

    const int qi = blockIdx.x;
    const int h = blockIdx.y;
    const int b = blockIdx.z;
    const int tid = threadIdx.x;
    const int tx4 = (tid & 15) * 4;
    const int ty4 = (tid >> 4) * 4;
    const size_t headoff = ((size_t)b * cfg::T) * cfg::D + (size_t)h * cfg::HD;
    const float scale = 0.125f;

#pragma unroll
    for (int it = 0; it < 4; it++) {
        int idx = tid + it * 256;
        int r = idx >> 4;
        int dq = (idx & 15) * 4;
        float4 t = *(const float4*)&q[headoff + (size_t)(qi * 64 + r) * cfg::D + dq];
        Qt[(dq + 0) * 64 + r] = t.x;
        Qt[(dq + 1) * 64 + r] = t.y;
        Qt[(dq + 2) * 64 + r] = t.z;
        Qt[(dq + 3) * 64 + r] = t.w;
    }

    float m_i[4], l_i[4], acc[4][4];
#pragma unroll
    for (int i = 0; i < 4; i++) {
        m_i[i] = -1e30f; l_i[i] = 0.f;
#pragma unroll
        for (int j = 0; j < 4; j++) acc[i][j] = 0.f;
    }

    for (int kt = 0; kt <= qi; kt++) {
#pragma unroll
        for (int it = 0; it < 4; it++) {
            int idx = tid + it * 256;
            int r = idx >> 4;
            int dq = (idx & 15) * 4;
            float4 t = *(const float4*)&k[headoff + (size_t)(kt * 64 + r) * cfg::D + dq];
            KVs[(dq + 0) * 64 + r] = t.x;
            KVs[(dq + 1) * 64 + r] = t.y;
            KVs[(dq + 2) * 64 + r] = t.z;
            KVs[(dq + 3) * 64 + r] = t.w;
        }
        __syncthreads();

        float s[4][4];
#pragma unroll
        for (int i = 0; i < 4; i++)
#pragma unroll
            for (int j = 0; j < 4; j++) s[i][j] = 0.f;
#pragma unroll 8
        for (int d = 0; d < 64; d++) {
            float a[4], bb[4];
            *(float4*)a = *(float4*)&Qt[d * 64 + ty4];
            *(float4*)bb = *(float4*)&KVs[d * 64 + tx4];
#pragma unroll
            for (int i = 0; i < 4; i++)
#pragma unroll
                for (int j = 0; j < 4; j++) s[i][j] += a[i] * bb[j];
        }

        const bool diag = (kt == qi);
        float mt[4];
#pragma unroll
        for (int i = 0; i < 4; i++) {
            mt[i] = -1e30f;
#pragma unroll
            for (int j = 0; j < 4; j++) {
                float sv = s[i][j] * scale;
                if (diag && (tx4 + j) > (ty4 + i)) sv = -1e30f;
                s[i][j] = sv;
                mt[i] = fmaxf(mt[i], sv);
            }
        }
#pragma unroll
        for (int i = 0; i < 4; i++)
#pragma unroll
            for (int off = 8; off; off >>= 1)
                mt[i] = fmaxf(mt[i], __shfl_xor_sync(0xffffffffu, mt[i], off));

        float alpha[4], rs[4];
#pragma unroll
        for (int i = 0; i < 4; i++) {
            float mnew = fmaxf(m_i[i], mt[i]);
            alpha[i] = expf(m_i[i] - mnew);
            m_i[i] = mnew;
            rs[i] = 0.f;
#pragma unroll
            for (int j = 0; j < 4; j++) {
                float p = expf(s[i][j] - mnew);
                s[i][j] = p;
                rs[i] += p;
            }
        }
#pragma unroll
        for (int i = 0; i < 4; i++)
#pragma unroll
            for (int off = 8; off; off >>= 1)
                rs[i] += __shfl_xor_sync(0xffffffffu, rs[i], off);
#pragma unroll
        for (int i = 0; i < 4; i++) {
            l_i[i] = l_i[i] * alpha[i] + rs[i];
#pragma unroll
            for (int j = 0; j < 4; j++) acc[i][j] *= alpha[i];
        }

#pragma unroll
        for (int i = 0; i < 4; i++)
            *(float4*)&Ps[(ty4 + i) * 64 + tx4] = *(float4*)&s[i][0];
        __syncthreads();

#pragma unroll
        for (int it = 0; it < 4; it++) {
            int idx = tid + it * 256;
            int r = idx >> 4;
            int dq = (idx & 15) * 4;
            *(float4*)&KVs[r * 64 + dq] =
                *(const float4*)&v[headoff + (size_t)(kt * 64 + r) * cfg::D + dq];
        }
        __syncthreads();

#pragma unroll 4
        for (int jj = 0; jj < 64; jj += 4) {
            float a[4][4];
#pragma unroll
            for (int i = 0; i < 4; i++)
                *(float4*)a[i] = *(float4*)&Ps[(ty4 + i) * 64 + jj];
#pragma unroll
            for (int c = 0; c < 4; c++) {
                float bb[4];
                *(float4*)bb = *(float4*)&KVs[(jj + c) * 64 + tx4];
#pragma unroll
                for (int i = 0; i < 4; i++)
#pragma unroll
                    for (int xcol = 0; xcol < 4; xcol++)
                        acc[i][xcol] += a[i][c] * bb[xcol];
            }
        }
        __syncthreads();
    }

#pragma unroll
    for (int i = 0; i < 4; i++) {
        float inv = 1.0f / l_i[i];
        int row = qi * 64 + ty4 + i;
        float4 r;
        r.x = acc[i][0] * inv; r.y = acc[i][1] * inv;
        r.z = acc[i][2] * inv; r.w = acc[i][3] * inv;
        *(float4*)&o[headoff + (size_t)row * cfg::D + tx4] = r;
    }
}

// ---------------- layernorm (unbiased std) ----------------------------------
__inline__ __device__ float block_reduce_sum(float val) {
    __shared__ float sbuf[8];
    int lane = threadIdx.x & 31, wid = threadIdx.x >> 5;
#pragma unroll
    for (int o = 16; o; o >>= 1) val += __shfl_xor_sync(0xffffffffu, val, o);
    if (lane == 0) sbuf[wid] = val;
    __syncthreads();
    val = (threadIdx.x < 8) ? sbuf[threadIdx.x] : 0.f;
    if (wid == 0) {
#pragma unroll
        for (int o = 4; o; o >>= 1) val += __shfl_xor_sync(0xffffffffu, val, o);
        if (lane == 0) sbuf[0] = val;
    }
    __syncthreads();
    float r = sbuf[0];
    __syncthreads();
    return r;
}

__global__ void layernorm_kernel(float* __restrict__ h, const float* __restrict__ g,
                                 const float* __restrict__ be) {
    int row = blockIdx.x;
    float* p = h + (size_t)row * cfg::D;
    int d0 = threadIdx.x * 4;
    float4 xv = *(float4*)&p[d0];
    float s = xv.x + xv.y + xv.z + xv.w;
    s = block_reduce_sum(s);
    float mean = s * (1.0f / cfg::D);
    float dx[4] = {xv.x - mean, xv.y - mean, xv.z - mean, xv.w - mean};
    float sq = dx[0] * dx[0] + dx[1] * dx[1] + dx[2] * dx[2] + dx[3] * dx[3];
    sq = block_reduce_sum(sq);
    float stdv = sqrtf(sq / (float)(cfg::D - 1));
    float inv = 1.0f / (stdv + cfg::EPS);
    float4 gg = *(const float4*)&g[d0];
    float4 bb = *(const float4*)&be[d0];
    float4 o;
    o.x = dx[0] * inv * gg.x + bb.x;
    o.y = dx[1] * inv * gg.y + bb.y;
    o.z = dx[2] * inv * gg.z + bb.z;
    o.w = dx[3] * inv * gg.w + bb.w;
    *(float4*)&p[d0] = o;
}

// ---------------- row softmax over V=32000 ----------------------------------
__global__ void softmax_kernel(float* __restrict__ out) {
    int row = blockIdx.x;
    float* p = out + (size_t)row * cfg::V;
    float m = -1e30f, s = 0.f;
    for (int j = threadIdx.x; j < cfg::V; j += 256) {
        float xv = p[j];
        if (xv > m) { s = s * expf(m - xv) + 1.0f; m = xv; }
        else        { s += expf(xv - m); }
    }
    __shared__ float sm[256], ss[256];
    sm[threadIdx.x] = m; ss[threadIdx.x] = s;
    __syncthreads();
    for (int off = 128; off; off >>= 1) {
        if (threadIdx.x < off) {
            float m1 = sm[threadIdx.x], s1 = ss[threadIdx.x];
            float m2 = sm[threadIdx.x + off], s2 = ss[threadIdx.x + off];
            float mm = fmaxf(m1, m2);
            sm[threadIdx.x] = mm;
            ss[threadIdx.x] = s1 * expf(m1 - mm) + s2 * expf(m2 - mm);
        }
        __syncthreads();
    }
    float mall = sm[0];
    float inv = 1.0f / ss[0];
    for (int j = threadIdx.x; j < cfg::V; j += 256) {
        p[j] = expf(p[j] - mall) * inv;
    }
}

// ---------------- host orchestration ---------------------------------------
extern "C" void kernel_launch(void* const* d_in, const int* in_sizes, int n_in,
                              void* d_out, int out_size) {
    using namespace cfg;
    const int*   x   = (const int*)d_in[0];
    const float* emb = (const float*)d_in[1];
    const float* Wq  = (const float*)d_in[2];
    const float* bq  = (const float*)d_in[3];
    const float* Wk  = (const float*)d_in[4];
    const float* bk  = (const float*)d_in[5];
    const float* Wv  = (const float*)d_in[6];
    const float* bv  = (const float*)d_in[7];
    const float* Wo  = (const float*)d_in[8];
    const float* bo  = (const float*)d_in[9];
    const float* g1  = (const float*)d_in[10];
    const float* be1 = (const float*)d_in[11];
    const float* W1  = (const float*)d_in[12];
    const float* bf1 = (const float*)d_in[13];
    const float* W2  = (const float*)d_in[14];
    const float* bf2 = (const float*)d_in[15];
    const float* g2  = (const float*)d_in[16];
    const float* be2 = (const float*)d_in[17];
    const float* Wl  = (const float*)d_in[18];
    const float* bl  = (const float*)d_in[19];
    float* out = (float*)d_out;

    float *h, *q, *k, *v, *o, *f;
    cudaGetSymbolAddress((void**)&h, g_h);
    cudaGetSymbolAddress((void**)&q, g_q);
    cudaGetSymbolAddress((void**)&k, g_k);
    cudaGetSymbolAddress((void**)&v, g_v);
    cudaGetSymbolAddress((void**)&o, g_o);
    cudaGetSymbolAddress((void**)&f, g_f);

    __nv_bfloat16 *ah, *al, *wqh, *wql, *wkh, *wkl, *wvh, *wvl, *woh, *wol;
    __nv_bfloat16 *w1h, *w1l, *w2h, *w2l, *wlh, *wll;
    cudaGetSymbolAddress((void**)&ah, g_ah);
    cudaGetSymbolAddress((void**)&al, g_al);
    cudaGetSymbolAddress((void**)&wqh, g_wqh); cudaGetSymbolAddress((void**)&wql, g_wql);
    cudaGetSymbolAddress((void**)&wkh, g_wkh); cudaGetSymbolAddress((void**)&wkl, g_wkl);
    cudaGetSymbolAddress((void**)&wvh, g_wvh); cudaGetSymbolAddress((void**)&wvl, g_wvl);
    cudaGetSymbolAddress((void**)&woh, g_woh); cudaGetSymbolAddress((void**)&wol, g_wol);
    cudaGetSymbolAddress((void**)&w1h, g_w1h); cudaGetSymbolAddress((void**)&w1l, g_w1l);
    cudaGetSymbolAddress((void**)&w2h, g_w2h); cudaGetSymbolAddress((void**)&w2l, g_w2l);
    cudaGetSymbolAddress((void**)&wlh, g_wlh); cudaGetSymbolAddress((void**)&wll, g_wll);

    cudaFuncSetAttribute(gemm_hmma<false>, cudaFuncAttributeMaxDynamicSharedMemorySize, GEMM_SMEM);
    cudaFuncSetAttribute(gemm_hmma<true>,  cudaFuncAttributeMaxDynamicSharedMemorySize, GEMM_SMEM);

    dim3 tb(32, 32);
    // weight prep: transpose+split  W[K,N] -> [N,K] hi/lo
    tsplit_kernel<<<dim3(D / 32, D / 32), tb>>>(Wq, wqh, wql, D, D);
    tsplit_kernel<<<dim3(D / 32, D / 32), tb>>>(Wk, wkh, wkl, D, D);
    tsplit_kernel<<<dim3(D / 32, D / 32), tb>>>(Wv, wvh, wvl, D, D);
    tsplit_kernel<<<dim3(D / 32, D / 32), tb>>>(Wo, woh, wol, D, D);
    tsplit_kernel<<<dim3(F / 32, D / 32), tb>>>(W1, w1h, w1l, D, F);   // [D,F]->[F,D]
    tsplit_kernel<<<dim3(D / 32, F / 32), tb>>>(W2, w2h, w2l, F, D);   // [F,D]->[D,F]
    tsplit_kernel<<<dim3(V / 32, D / 32), tb>>>(Wl, wlh, wll, D, V);   // [D,V]->[V,D]

    embed_kernel<<<M, 256>>>(x, emb, h);
    split_kernel<<<(M * D / 4 + 255) / 256, 256>>>(h, ah, al, M * D / 4);

    gemm_hmma<false><<<dim3(M / 128, D / 256), 512, GEMM_SMEM>>>(ah, al, wqh, wql, bq, q, D, D);
    gemm_hmma<false><<<dim3(M / 128, D / 256), 512, GEMM_SMEM>>>(ah, al, wkh, wkl, bk, k, D, D);
    gemm_hmma<false><<<dim3(M / 128, D / 256), 512, GEMM_SMEM>>>(ah, al, wvh, wvl, bv, v, D, D);

    flash_kernel<<<dim3(T / 64, H, B), 256>>>(q, k, v, o);

    split_kernel<<<(M * D / 4 + 255) / 256, 256>>>(o, ah, al, M * D / 4);
    gemm_hmma<false><<<dim3(M / 128, D / 256), 512, GEMM_SMEM>>>(ah, al, woh, wol, bo, h, D, D);
    layernorm_kernel<<<M, 256>>>(h, g1, be1);

    split_kernel<<<(M * D / 4 + 255) / 256, 256>>>(h, ah, al, M * D / 4);
    gemm_hmma<true><<<dim3(M / 128, F / 256), 512, GEMM_SMEM>>>(ah, al, w1h, w1l, bf1, f, F, D);

    split_kernel<<<((size_t)M * F / 4 + 255) / 256, 256>>>(f, ah, al, M * F / 4);
    gemm_hmma<false><<<dim3(M / 128, D / 256), 512, GEMM_SMEM>>>(ah, al, w2h, w2l, bf2, o, D, F);
    layernorm_kernel<<<M, 256>>>(o, g2, be2);

    split_kernel<<<(M * D / 4 + 255) / 256, 256>>>(o, ah, al, M * D / 4);
    gemm_hmma<false><<<dim3(M / 128, V / 256), 512, GEMM_SMEM>>>(ah, al, wlh, wll, bl, out, V, D);

    softmax_kernel<<<M, 256>>>(out);
}

// round 4
// speedup vs baseline: 1.8418x; 1.0718x over previous
#include <cuda_runtime.h>
#include <cuda_bf16.h>
#include <math.h>
#include <stdint.h>

// ---------------- problem constants ----------------
namespace cfg {
constexpr int B = 2, T = 2048, D = 1024, H = 16, HD = 64, F = 4096, V = 32000;
constexpr int M = B * T;
constexpr float EPS = 1e-6f;
}

// ---------------- scratch ----------------------------------------------------
__device__ float g_h[cfg::M * cfg::D];
__device__ float g_q[cfg::M * cfg::D];
__device__ float g_k[cfg::M * cfg::D];
__device__ float g_v[cfg::M * cfg::D];
__device__ float g_o[cfg::M * cfg::D];
__device__ float g_f[(size_t)cfg::M * cfg::F];

__device__ __nv_bfloat16 g_ah[(size_t)cfg::M * cfg::F];
__device__ __nv_bfloat16 g_al[(size_t)cfg::M * cfg::F];
__device__ __nv_bfloat16 g_wqh[cfg::D * cfg::D], g_wql[cfg::D * cfg::D];
__device__ __nv_bfloat16 g_wkh[cfg::D * cfg::D], g_wkl[cfg::D * cfg::D];
__device__ __nv_bfloat16 g_wvh[cfg::D * cfg::D], g_wvl[cfg::D * cfg::D];
__device__ __nv_bfloat16 g_woh[cfg::D * cfg::D], g_wol[cfg::D * cfg::D];
__device__ __nv_bfloat16 g_w1h[(size_t)cfg::D * cfg::F], g_w1l[(size_t)cfg::D * cfg::F];
__device__ __nv_bfloat16 g_w2h[(size_t)cfg::D * cfg::F], g_w2l[(size_t)cfg::D * cfg::F];
__device__ __nv_bfloat16 g_wlh[(size_t)cfg::V * cfg::D], g_wll[(size_t)cfg::V * cfg::D];

// ---------------- PTX helpers -------------------------------------------------
__device__ __forceinline__ uint32_t smem_u32(const void* p) {
    uint32_t a;
    asm("{ .reg .u64 t; cvta.to.shared.u64 t, %1; cvt.u32.u64 %0, t; }" : "=r"(a) : "l"(p));
    return a;
}
__device__ __forceinline__ void cp16(uint32_t dst, const void* src) {
    asm volatile("cp.async.cg.shared.global [%0], [%1], 16;" :: "r"(dst), "l"(src));
}
__device__ __forceinline__ void cp_commit() {
    asm volatile("cp.async.commit_group;" ::: "memory");
}
template <int N>
__device__ __forceinline__ void cp_wait() {
    asm volatile("cp.async.wait_group %0;" :: "n"(N) : "memory");
}
__device__ __forceinline__ void ldmat4(uint32_t* r, uint32_t addr) {
    asm volatile("ldmatrix.sync.aligned.m8n8.x4.shared.b16 {%0,%1,%2,%3}, [%4];"
                 : "=r"(r[0]), "=r"(r[1]), "=r"(r[2]), "=r"(r[3]) : "r"(addr));
}
__device__ __forceinline__ void mma16816(float* c, const uint32_t* a, uint32_t b0, uint32_t b1) {
    asm volatile(
        "mma.sync.aligned.m16n8k16.row.col.f32.bf16.bf16.f32 "
        "{%0,%1,%2,%3}, {%4,%5,%6,%7}, {%8,%9}, {%0,%1,%2,%3};"
        : "+f"(c[0]), "+f"(c[1]), "+f"(c[2]), "+f"(c[3])
        : "r"(a[0]), "r"(a[1]), "r"(a[2]), "r"(a[3]), "r"(b0), "r"(b1));
}
__device__ __forceinline__ uint32_t pack_bf16(float x, float y) {
    __nv_bfloat162 t = __floats2bfloat162_rn(x, y);
    return *(uint32_t*)&t;
}

// ---------------- fused bf16x3 GEMM on HMMA -----------------------------------
// C[M,N] = A@B^T (+bias, opt ReLU). B pre-transposed [N,K]. Per K16 chunk load
// Ah,Al,Bh,Bl once; issue 3 products. CTA 128x256, 512 thr (16 warps 2x8),
// 4-stage cp.async. Row stride 48B (conflict-free).
static constexpr uint32_t GA_BYTES = 128 * 48;            // 6144
static constexpr uint32_t GB_BYTES = 256 * 48;            // 12288
static constexpr uint32_t GSTAGE = 2 * GA_BYTES + 2 * GB_BYTES;  // 36864
static constexpr uint32_t GEMM_SMEM = 4 * GSTAGE;          // 147456

template <bool RELU>
__global__ __launch_bounds__(512, 1) void gemm_hmma(
    const __nv_bfloat16* __restrict__ Ah, const __nv_bfloat16* __restrict__ Al,
    const __nv_bfloat16* __restrict__ Bh, const __nv_bfloat16* __restrict__ Bl,
    const float* __restrict__ bias, float* __restrict__ C, int Nd, int Kd) {
    extern __shared__ char smem[];
    const uint32_t sb = smem_u32(smem);
    const int tid = threadIdx.x;
    const int wid = tid >> 5, lane = tid & 31;
    const int wm = wid & 1, wn = wid >> 1;
    const int bm = blockIdx.x * 128;
    const int bn = blockIdx.y * 256;
    const int NC = Kd >> 4;

    const int r2 = tid >> 1, s2 = tid & 1;  // row/seg for loads

    auto issue_chunk = [&](int c) {
        const int lk = c << 4;
        uint32_t base = sb + (c & 3) * GSTAGE;
        if (tid < 256) {
            cp16(base + r2 * 48 + s2 * 16, Ah + (size_t)(bm + r2) * Kd + lk + s2 * 8);
        } else {
            int rr = (tid - 256) >> 1, ss = (tid - 256) & 1;
            cp16(base + GA_BYTES + rr * 48 + ss * 16,
                 Al + (size_t)(bm + rr) * Kd + lk + ss * 8);
        }
        cp16(base + 2 * GA_BYTES + r2 * 48 + s2 * 16,
             Bh + (size_t)(bn + r2) * Kd + lk + s2 * 8);
        cp16(base + 2 * GA_BYTES + GB_BYTES + r2 * 48 + s2 * 16,
             Bl + (size_t)(bn + r2) * Kd + lk + s2 * 8);
    };

    issue_chunk(0); cp_commit();
    issue_chunk(1); cp_commit();
    issue_chunk(2); cp_commit();

    float acc[4][4][4];
#pragma unroll
    for (int i = 0; i < 4; i++)
#pragma unroll
        for (int j = 0; j < 4; j++)
#pragma unroll
            for (int r = 0; r < 4; r++) acc[i][j][r] = 0.f;

    const int a_r = lane & 15;
    const int a_c = (lane >> 4) << 3;
    const int b_r = (lane & 7) + ((lane >> 4) << 3);
    const int b_c = ((lane >> 3) & 1) << 3;

    for (int c = 0; c < NC; c++) {
        cp_wait<2>();
        __syncthreads();
        if (c + 3 < NC) issue_chunk(c + 3);
        cp_commit();

        const uint32_t base = sb + (c & 3) * GSTAGE;
        const uint32_t sAh = base, sAl = base + GA_BYTES;
        const uint32_t sBh = base + 2 * GA_BYTES, sBl = sBh + GB_BYTES;

        uint32_t aH[4][4], aL[4][4], bH[2][4], bL[2][4];
#pragma unroll
        for (int mt = 0; mt < 4; mt++)
            ldmat4(aH[mt], sAh + (uint32_t)(wm * 64 + mt * 16 + a_r) * 48 + a_c * 2);
#pragma unroll
        for (int g = 0; g < 2; g++)
            ldmat4(bH[g], sBh + (uint32_t)(wn * 32 + g * 16 + b_r) * 48 + b_c * 2);
#pragma unroll
        for (int mt = 0; mt < 4; mt++)
#pragma unroll
            for (int nt = 0; nt < 4; nt++)
                mma16816(acc[mt][nt], aH[mt], bH[nt >> 1][(nt & 1) * 2], bH[nt >> 1][(nt & 1) * 2 + 1]);
#pragma unroll
        for (int mt = 0; mt < 4; mt++)
            ldmat4(aL[mt], sAl + (uint32_t)(wm * 64 + mt * 16 + a_r) * 48 + a_c * 2);
#pragma unroll
        for (int mt = 0; mt < 4; mt++)
#pragma unroll
            for (int nt = 0; nt < 4; nt++)
                mma16816(acc[mt][nt], aL[mt], bH[nt >> 1][(nt & 1) * 2], bH[nt >> 1][(nt & 1) * 2 + 1]);
#pragma unroll
        for (int g = 0; g < 2; g++)
            ldmat4(bL[g], sBl + (uint32_t)(wn * 32 + g * 16 + b_r) * 48 + b_c * 2);
#pragma unroll
        for (int mt = 0; mt < 4; mt++)
#pragma unroll
            for (int nt = 0; nt < 4; nt++)
                mma16816(acc[mt][nt], aH[mt], bL[nt >> 1][(nt & 1) * 2], bL[nt >> 1][(nt & 1) * 2 + 1]);
    }

    const int g = lane >> 2, t = lane & 3;
#pragma unroll
    for (int mt = 0; mt < 4; mt++) {
#pragma unroll
        for (int nt = 0; nt < 4; nt++) {
            int row0 = bm + wm * 64 + mt * 16 + g;
            int col = bn + wn * 32 + nt * 8 + t * 2;
            float bx = bias[col], by = bias[col + 1];
            float2 v0, v1;
            v0.x = acc[mt][nt][0] + bx; v0.y = acc[mt][nt][1] + by;
            v1.x = acc[mt][nt][2] + bx; v1.y = acc[mt][nt][3] + by;
            if (RELU) {
                v0.x = fmaxf(v0.x, 0.f); v0.y = fmaxf(v0.y, 0.f);
                v1.x = fmaxf(v1.x, 0.f); v1.y = fmaxf(v1.y, 0.f);
            }
            *(float2*)&C[(size_t)row0 * Nd + col] = v0;
            *(float2*)&C[(size_t)(row0 + 8) * Nd + col] = v1;
        }
    }
}

// ---------------- HMMA flash attention (bf16x3, causal) -----------------------
// 64x64 tiles, 128 threads (4 warps, warp = 16 q-rows x 64 cols).
static constexpr int FSTR = 72;  // bf16 row stride (144B, conflict-free)

__global__ __launch_bounds__(128) void flash_hmma(
    const float* __restrict__ q, const float* __restrict__ k,
    const float* __restrict__ v, float* __restrict__ o) {
    __shared__ __nv_bfloat16 sQh[64 * FSTR], sQl[64 * FSTR];
    __shared__ __nv_bfloat16 sKh[64 * FSTR], sKl[64 * FSTR];
    __shared__ __nv_bfloat16 sVh[64 * FSTR], sVl[64 * FSTR];

    const int qi = gridDim.x - 1 - blockIdx.x;   // big tiles first
    const int h = blockIdx.y, b = blockIdx.z;
    const int tid = threadIdx.x;
    const int wid = tid >> 5, lane = tid & 31;
    const size_t headoff = ((size_t)b * cfg::T) * cfg::D + (size_t)h * cfg::HD;

    const uint32_t uQh = smem_u32(sQh), uQl = smem_u32(sQl);
    const uint32_t uKh = smem_u32(sKh), uKl = smem_u32(sKl);
    const uint32_t uVh = smem_u32(sVh), uVl = smem_u32(sVl);

    const int a_r = lane & 15;
    const int a_c = (lane >> 4) << 3;
    const int b_r = (lane & 7) + ((lane >> 4) << 3);
    const int b_c = ((lane >> 3) & 1) << 3;
    const int g = lane >> 2, t = lane & 3;

    // load + split Q tile
#pragma unroll
    for (int it = 0; it < 8; it++) {
        int idx = tid + it * 128;            // 1024 float4 slots
        int r = idx >> 4, dq = (idx & 15) * 4;
        float4 tv = *(const float4*)&q[headoff + (size_t)(qi * 64 + r) * cfg::D + dq];
        uint32_t h01 = pack_bf16(tv.x, tv.y);
        uint32_t h23 = pack_bf16(tv.z, tv.w);
        *(uint2*)&sQh[r * FSTR + dq] = make_uint2(h01, h23);
        __nv_bfloat162 hh0 = *(__nv_bfloat162*)&h01;
        __nv_bfloat162 hh1 = *(__nv_bfloat162*)&h23;
        uint32_t l01 = pack_bf16(tv.x - __bfloat162float(hh0.x), tv.y - __bfloat162float(hh0.y));
        uint32_t l23 = pack_bf16(tv.z - __bfloat162float(hh1.x), tv.w - __bfloat162float(hh1.y));
        *(uint2*)&sQl[r * FSTR + dq] = make_uint2(l01, l23);
    }

    float accO[8][4];
#pragma unroll
    for (int i = 0; i < 8; i++)
#pragma unroll
        for (int j = 0; j < 4; j++) accO[i][j] = 0.f;
    float m0 = -1e30f, m1 = -1e30f, l0 = 0.f, l1 = 0.f;

    for (int kt = 0; kt <= qi; kt++) {
        __syncthreads();   // prior iter done reading K/V smem
        // load + split K tile (natural) and V tile (transposed)
#pragma unroll
        for (int it = 0; it < 8; it++) {
            int idx = tid + it * 128;
            int r = idx >> 4, dq = (idx & 15) * 4;
            float4 tv = *(const float4*)&k[headoff + (size_t)(kt * 64 + r) * cfg::D + dq];
            uint32_t h01 = pack_bf16(tv.x, tv.y);
            uint32_t h23 = pack_bf16(tv.z, tv.w);
            *(uint2*)&sKh[r * FSTR + dq] = make_uint2(h01, h23);
            __nv_bfloat162 hh0 = *(__nv_bfloat162*)&h01;
            __nv_bfloat162 hh1 = *(__nv_bfloat162*)&h23;
            uint32_t l01 = pack_bf16(tv.x - __bfloat162float(hh0.x), tv.y - __bfloat162float(hh0.y));
            uint32_t l23 = pack_bf16(tv.z - __bfloat162float(hh1.x), tv.w - __bfloat162float(hh1.y));
            *(uint2*)&sKl[r * FSTR + dq] = make_uint2(l01, l23);

            float4 vv = *(const float4*)&v[headoff + (size_t)(kt * 64 + r) * cfg::D + dq];
            float vals[4] = {vv.x, vv.y, vv.z, vv.w};
#pragma unroll
            for (int j = 0; j < 4; j++) {
                __nv_bfloat16 hb = __float2bfloat16_rn(vals[j]);
                sVh[(dq + j) * FSTR + r] = hb;
                sVl[(dq + j) * FSTR + r] = __float2bfloat16_rn(vals[j] - __bfloat162float(hb));
            }
        }
        __syncthreads();

        // S = Qh*Kh + Qh*Kl + Ql*Kh
        float sa[8][4];
#pragma unroll
        for (int i = 0; i < 8; i++)
#pragma unroll
            for (int j = 0; j < 4; j++) sa[i][j] = 0.f;

        const uint32_t qsrc[3] = {uQh, uQh, uQl};
        const uint32_t ksrc[3] = {uKh, uKl, uKh};
#pragma unroll
        for (int cb = 0; cb < 3; cb++) {
#pragma unroll
            for (int kg = 0; kg < 4; kg++) {
                uint32_t af[4];
                ldmat4(af, qsrc[cb] + (uint32_t)(wid * 16 + a_r) * (FSTR * 2) + (kg * 16 + a_c) * 2);
#pragma unroll
                for (int gg = 0; gg < 4; gg++) {
                    uint32_t bf[4];
                    ldmat4(bf, ksrc[cb] + (uint32_t)(gg * 16 + b_r) * (FSTR * 2) + (kg * 16 + b_c) * 2);
                    mma16816(sa[gg * 2], af, bf[0], bf[1]);
                    mma16816(sa[gg * 2 + 1], af, bf[2], bf[3]);
                }
            }
        }

        // scale + causal mask
        const bool diag = (kt == qi);
#pragma unroll
        for (int nt = 0; nt < 8; nt++) {
            int c0 = nt * 8 + t * 2;
            sa[nt][0] *= 0.125f; sa[nt][1] *= 0.125f;
            sa[nt][2] *= 0.125f; sa[nt][3] *= 0.125f;
            if (diag) {
                int r0 = wid * 16 + g, r1 = r0 + 8;
                if (c0 > r0)     sa[nt][0] = -1e30f;
                if (c0 + 1 > r0) sa[nt][1] = -1e30f;
                if (c0 > r1)     sa[nt][2] = -1e30f;
                if (c0 + 1 > r1) sa[nt][3] = -1e30f;
            }
        }

        // row max (per-thread over 16 cols, then quad butterfly)
        float mt0 = -1e30f, mt1 = -1e30f;
#pragma unroll
        for (int nt = 0; nt < 8; nt++) {
            mt0 = fmaxf(mt0, fmaxf(sa[nt][0], sa[nt][1]));
            mt1 = fmaxf(mt1, fmaxf(sa[nt][2], sa[nt][3]));
        }
#pragma unroll
        for (int off = 1; off <= 2; off <<= 1) {
            mt0 = fmaxf(mt0, __shfl_xor_sync(0xffffffffu, mt0, off));
            mt1 = fmaxf(mt1, __shfl_xor_sync(0xffffffffu, mt1, off));
        }
        float mn0 = fmaxf(m0, mt0), mn1 = fmaxf(m1, mt1);
        float al0 = __expf(m0 - mn0), al1 = __expf(m1 - mn1);
        m0 = mn0; m1 = mn1;

        float rs0 = 0.f, rs1 = 0.f;
#pragma unroll
        for (int nt = 0; nt < 8; nt++) {
            sa[nt][0] = __expf(sa[nt][0] - mn0);
            sa[nt][1] = __expf(sa[nt][1] - mn0);
            sa[nt][2] = __expf(sa[nt][2] - mn1);
            sa[nt][3] = __expf(sa[nt][3] - mn1);
            rs0 += sa[nt][0] + sa[nt][1];
            rs1 += sa[nt][2] + sa[nt][3];
        }
#pragma unroll
        for (int off = 1; off <= 2; off <<= 1) {
            rs0 += __shfl_xor_sync(0xffffffffu, rs0, off);
            rs1 += __shfl_xor_sync(0xffffffffu, rs1, off);
        }
        l0 = l0 * al0 + rs0;
        l1 = l1 * al1 + rs1;
#pragma unroll
        for (int nt = 0; nt < 8; nt++) {
            accO[nt][0] *= al0; accO[nt][1] *= al0;
            accO[nt][2] *= al1; accO[nt][3] *= al1;
        }

        // P fragments (hi/lo) straight from accumulators
        uint32_t ph[4][4], pl[4][4];
#pragma unroll
        for (int kg = 0; kg < 4; kg++) {
            float p00 = sa[2 * kg][0],     p01 = sa[2 * kg][1];
            float p10 = sa[2 * kg][2],     p11 = sa[2 * kg][3];
            float p20 = sa[2 * kg + 1][0], p21 = sa[2 * kg + 1][1];
            float p30 = sa[2 * kg + 1][2], p31 = sa[2 * kg + 1][3];
            ph[kg][0] = pack_bf16(p00, p01);
            ph[kg][1] = pack_bf16(p10, p11);
            ph[kg][2] = pack_bf16(p20, p21);
            ph[kg][3] = pack_bf16(p30, p31);
            __nv_bfloat162 h0 = *(__nv_bfloat162*)&ph[kg][0];
            __nv_bfloat162 h1 = *(__nv_bfloat162*)&ph[kg][1];
            __nv_bfloat162 h2 = *(__nv_bfloat162*)&ph[kg][2];
            __nv_bfloat162 h3 = *(__nv_bfloat162*)&ph[kg][3];
            pl[kg][0] = pack_bf16(p00 - __bfloat162float(h0.x), p01 - __bfloat162float(h0.y));
            pl[kg][1] = pack_bf16(p10 - __bfloat162float(h1.x), p11 - __bfloat162float(h1.y));
            pl[kg][2] = pack_bf16(p20 - __bfloat162float(h2.x), p21 - __bfloat162float(h2.y));
            pl[kg][3] = pack_bf16(p30 - __bfloat162float(h3.x), p31 - __bfloat162float(h3.y));
        }

        // O += Ph*Vh + Ph*Vl + Pl*Vh
        const uint32_t vsrc[3] = {uVh, uVl, uVh};
#pragma unroll
        for (int cb = 0; cb < 3; cb++) {
            uint32_t (*pf)[4] = (cb == 2) ? pl : ph;
#pragma unroll
            for (int kg = 0; kg < 4; kg++) {
#pragma unroll
                for (int gg = 0; gg < 4; gg++) {
                    uint32_t bf[4];
                    ldmat4(bf, vsrc[cb] + (uint32_t)(gg * 16 + b_r) * (FSTR * 2) + (kg * 16 + b_c) * 2);
                    mma16816(accO[gg * 2], pf[kg], bf[0], bf[1]);
                    mma16816(accO[gg * 2 + 1], pf[kg], bf[2], bf[3]);
                }
            }
        }
    }

    float inv0 = 1.0f / l0, inv1 = 1.0f / l1;
    int row0 = qi * 64 + wid * 16 + g;
#pragma unroll
    for (int nt = 0; nt < 8; nt++) {
        int col = nt * 8 + t * 2;
        float2 v0 = make_float2(accO[nt][0] * inv0, accO[nt][1] * inv0);
        float2 v1 = make_float2(accO[nt][2] * inv1, accO[nt][3] * inv1);
        *(float2*)&o[headoff + (size_t)row0 * cfg::D + col] = v0;
        *(float2*)&o[headoff + (size_t)(row0 + 8) * cfg::D + col] = v1;
    }
}

// ---------------- split fp32 -> bf16 hi/lo ------------------------------------
__global__ void split_kernel(const float* __restrict__ x, __nv_bfloat16* __restrict__ hi,
                             __nv_bfloat16* __restrict__ lo, int n4) {
    int i = blockIdx.x * blockDim.x + threadIdx.x;
    if (i >= n4) return;
    float4 v = ((const float4*)x)[i];
    __nv_bfloat16 h0 = __float2bfloat16_rn(v.x);
    __nv_bfloat16 h1 = __float2bfloat16_rn(v.y);
    __nv_bfloat16 h2 = __float2bfloat16_rn(v.z);
    __nv_bfloat16 h3 = __float2bfloat16_rn(v.w);
    ((__nv_bfloat162*)hi)[i * 2 + 0] = __halves2bfloat162(h0, h1);
    ((__nv_bfloat162*)hi)[i * 2 + 1] = __halves2bfloat162(h2, h3);
    __nv_bfloat16 l0 = __float2bfloat16_rn(v.x - __bfloat162float(h0));
    __nv_bfloat16 l1 = __float2bfloat16_rn(v.y - __bfloat162float(h1));
    __nv_bfloat16 l2 = __float2bfloat16_rn(v.z - __bfloat162float(h2));
    __nv_bfloat16 l3 = __float2bfloat16_rn(v.w - __bfloat162float(h3));
    ((__nv_bfloat162*)lo)[i * 2 + 0] = __halves2bfloat162(l0, l1);
    ((__nv_bfloat162*)lo)[i * 2 + 1] = __halves2bfloat162(l2, l3);
}

// ---------------- transpose + split weight: W[K,N] -> hi/lo [N,K] --------------
__global__ void tsplit_kernel(const float* __restrict__ W, __nv_bfloat16* __restrict__ hi,
                              __nv_bfloat16* __restrict__ lo, int K, int N) {
    __shared__ float s[32][33];
    int n = blockIdx.x * 32 + threadIdx.x;
    int k = blockIdx.y * 32 + threadIdx.y;
    s[threadIdx.y][threadIdx.x] = W[(size_t)k * N + n];
    __syncthreads();
    int no = blockIdx.x * 32 + threadIdx.y;
    int ko = blockIdx.y * 32 + threadIdx.x;
    float v = s[threadIdx.x][threadIdx.y];
    __nv_bfloat16 h = __float2bfloat16_rn(v);
    hi[(size_t)no * K + ko] = h;
    lo[(size_t)no * K + ko] = __float2bfloat16_rn(v - __bfloat162float(h));
}

// ---------------- embed + positional encoding ---------------------------------
__global__ void embed_kernel(const int* __restrict__ x, const float* __restrict__ emb,
                             float* __restrict__ h) {
    int row = blockIdx.x;
    int t = row & (cfg::T - 1);
    int tok = x[row];
    const float* e = emb + (size_t)tok * cfg::D;
    float* out = h + (size_t)row * cfg::D;
    int d0 = threadIdx.x * 4;
    float4 ev = *(const float4*)&e[d0];
    const float cfac = -0.017988946039015984f;
    int i0 = d0 >> 1;
    float f0 = expf((float)i0 * cfac);
    float f1 = expf((float)(i0 + 1) * cfac);
    float a0 = (float)t * f0, a1 = (float)t * f1;
    float4 o;
    o.x = ev.x + sinf(a0);
    o.y = ev.y + cosf(a0);
    o.z = ev.z + sinf(a1);
    o.w = ev.w + cosf(a1);
    *(float4*)&out[d0] = o;
}

// ---------------- layernorm (unbiased std) -------------------------------------
__inline__ __device__ float block_reduce_sum(float val) {
    __shared__ float sbuf[8];
    int lane = threadIdx.x & 31, wid = threadIdx.x >> 5;
#pragma unroll
    for (int o = 16; o; o >>= 1) val += __shfl_xor_sync(0xffffffffu, val, o);
    if (lane == 0) sbuf[wid] = val;
    __syncthreads();
    val = (threadIdx.x < 8) ? sbuf[threadIdx.x] : 0.f;
    if (wid == 0) {
#pragma unroll
        for (int o = 4; o; o >>= 1) val += __shfl_xor_sync(0xffffffffu, val, o);
        if (lane == 0) sbuf[0] = val;
    }
    __syncthreads();
    float r = sbuf[0];
    __syncthreads();
    return r;
}

__global__ void layernorm_kernel(float* __restrict__ h, const float* __restrict__ g,
                                 const float* __restrict__ be) {
    int row = blockIdx.x;
    float* p = h + (size_t)row * cfg::D;
    int d0 = threadIdx.x * 4;
    float4 xv = *(float4*)&p[d0];
    float s = xv.x + xv.y + xv.z + xv.w;
    s = block_reduce_sum(s);
    float mean = s * (1.0f / cfg::D);
    float dx[4] = {xv.x - mean, xv.y - mean, xv.z - mean, xv.w - mean};
    float sq = dx[0] * dx[0] + dx[1] * dx[1] + dx[2] * dx[2] + dx[3] * dx[3];
    sq = block_reduce_sum(sq);
    float stdv = sqrtf(sq / (float)(cfg::D - 1));
    float inv = 1.0f / (stdv + cfg::EPS);
    float4 gg = *(const float4*)&g[d0];
    float4 bb = *(const float4*)&be[d0];
    float4 o;
    o.x = dx[0] * inv * gg.x + bb.x;
    o.y = dx[1] * inv * gg.y + bb.y;
    o.z = dx[2] * inv * gg.z + bb.z;
    o.w = dx[3] * inv * gg.w + bb.w;
    *(float4*)&p[d0] = o;
}

// ---------------- row softmax over V=32000 -------------------------------------
__global__ void softmax_kernel(float* __restrict__ out) {
    int row = blockIdx.x;
    float* p = out + (size_t)row * cfg::V;
    float m = -1e30f, s = 0.f;
    for (int j = threadIdx.x; j < cfg::V; j += 256) {
        float xv = p[j];
        if (xv > m) { s = s * __expf(m - xv) + 1.0f; m = xv; }
        else        { s += __expf(xv - m); }
    }
    __shared__ float sm[256], ss[256];
    sm[threadIdx.x] = m; ss[threadIdx.x] = s;
    __syncthreads();
    for (int off = 128; off; off >>= 1) {
        if (threadIdx.x < off) {
            float m1 = sm[threadIdx.x], s1 = ss[threadIdx.x];
            float m2 = sm[threadIdx.x + off], s2 = ss[threadIdx.x + off];
            float mm = fmaxf(m1, m2);
            sm[threadIdx.x] = mm;
            ss[threadIdx.x] = s1 * __expf(m1 - mm) + s2 * __expf(m2 - mm);
        }
        __syncthreads();
    }
    float mall = sm[0];
    float inv = 1.0f / ss[0];
    for (int j = threadIdx.x; j < cfg::V; j += 256) {
        p[j] = __expf(p[j] - mall) * inv;
    }
}

// ---------------- host orchestration -------------------------------------------
extern "C" void kernel_launch(void* const* d_in, const int* in_sizes, int n_in,
                              void* d_out, int out_size) {
    using namespace cfg;
    const int*   x   = (const int*)d_in[0];
    const float* emb = (const float*)d_in[1];
    const float* Wq  = (const float*)d_in[2];
    const float* bq  = (const float*)d_in[3];
    const float* Wk  = (const float*)d_in[4];
    const float* bk  = (const float*)d_in[5];
    const float* Wv  = (const float*)d_in[6];
    const float* bv  = (const float*)d_in[7];
    const float* Wo  = (const float*)d_in[8];
    const float* bo  = (const float*)d_in[9];
    const float* g1  = (const float*)d_in[10];
    const float* be1 = (const float*)d_in[11];
    const float* W1  = (const float*)d_in[12];
    const float* bf1 = (const float*)d_in[13];
    const float* W2  = (const float*)d_in[14];
    const float* bf2 = (const float*)d_in[15];
    const float* g2  = (const float*)d_in[16];
    const float* be2 = (const float*)d_in[17];
    const float* Wl  = (const float*)d_in[18];
    const float* bl  = (const float*)d_in[19];
    float* out = (float*)d_out;

    float *h, *q, *k, *v, *o, *f;
    cudaGetSymbolAddress((void**)&h, g_h);
    cudaGetSymbolAddress((void**)&q, g_q);
    cudaGetSymbolAddress((void**)&k, g_k);
    cudaGetSymbolAddress((void**)&v, g_v);
    cudaGetSymbolAddress((void**)&o, g_o);
    cudaGetSymbolAddress((void**)&f, g_f);

    __nv_bfloat16 *ah, *al, *wqh, *wql, *wkh, *wkl, *wvh, *wvl, *woh, *wol;
    __nv_bfloat16 *w1h, *w1l, *w2h, *w2l, *wlh, *wll;
    cudaGetSymbolAddress((void**)&ah, g_ah);
    cudaGetSymbolAddress((void**)&al, g_al);
    cudaGetSymbolAddress((void**)&wqh, g_wqh); cudaGetSymbolAddress((void**)&wql, g_wql);
    cudaGetSymbolAddress((void**)&wkh, g_wkh); cudaGetSymbolAddress((void**)&wkl, g_wkl);
    cudaGetSymbolAddress((void**)&wvh, g_wvh); cudaGetSymbolAddress((void**)&wvl, g_wvl);
    cudaGetSymbolAddress((void**)&woh, g_woh); cudaGetSymbolAddress((void**)&wol, g_wol);
    cudaGetSymbolAddress((void**)&w1h, g_w1h); cudaGetSymbolAddress((void**)&w1l, g_w1l);
    cudaGetSymbolAddress((void**)&w2h, g_w2h); cudaGetSymbolAddress((void**)&w2l, g_w2l);
    cudaGetSymbolAddress((void**)&wlh, g_wlh); cudaGetSymbolAddress((void**)&wll, g_wll);

    cudaFuncSetAttribute(gemm_hmma<false>, cudaFuncAttributeMaxDynamicSharedMemorySize, GEMM_SMEM);
    cudaFuncSetAttribute(gemm_hmma<true>,  cudaFuncAttributeMaxDynamicSharedMemorySize, GEMM_SMEM);

    dim3 tb(32, 32);
    tsplit_kernel<<<dim3(D / 32, D / 32), tb>>>(Wq, wqh, wql, D, D);
    tsplit_kernel<<<dim3(D / 32, D / 32), tb>>>(Wk, wkh, wkl, D, D);
    tsplit_kernel<<<dim3(D / 32, D / 32), tb>>>(Wv, wvh, wvl, D, D);
    tsplit_kernel<<<dim3(D / 32, D / 32), tb>>>(Wo, woh, wol, D, D);
    tsplit_kernel<<<dim3(F / 32, D / 32), tb>>>(W1, w1h, w1l, D, F);
    tsplit_kernel<<<dim3(D / 32, F / 32), tb>>>(W2, w2h, w2l, F, D);
    tsplit_kernel<<<dim3(V / 32, D / 32), tb>>>(Wl, wlh, wll, D, V);

    embed_kernel<<<M, 256>>>(x, emb, h);
    split_kernel<<<(M * D / 4 + 255) / 256, 256>>>(h, ah, al, M * D / 4);

    gemm_hmma<false><<<dim3(M / 128, D / 256), 512, GEMM_SMEM>>>(ah, al, wqh, wql, bq, q, D, D);
    gemm_hmma<false><<<dim3(M / 128, D / 256), 512, GEMM_SMEM>>>(ah, al, wkh, wkl, bk, k, D, D);
    gemm_hmma<false><<<dim3(M / 128, D / 256), 512, GEMM_SMEM>>>(ah, al, wvh, wvl, bv, v, D, D);

    flash_hmma<<<dim3(T / 64, H, B), 128>>>(q, k, v, o);

    split_kernel<<<(M * D / 4 + 255) / 256, 256>>>(o, ah, al, M * D / 4);
    gemm_hmma<false><<<dim3(M / 128, D / 256), 512, GEMM_SMEM>>>(ah, al, woh, wol, bo, h, D, D);
    layernorm_kernel<<<M, 256>>>(h, g1, be1);

    split_kernel<<<(M * D / 4 + 255) / 256, 256>>>(h, ah, al, M * D / 4);
    gemm_hmma<true><<<dim3(M / 128, F / 256), 512, GEMM_SMEM>>>(ah, al, w1h, w1l, bf1, f, F, D);

    split_kernel<<<((size_t)M * F / 4 + 255) / 256, 256>>>(f, ah, al, M * F / 4);
    gemm_hmma<false><<<dim3(M / 128, D / 256), 512, GEMM_SMEM>>>(ah, al, w2h, w2l, bf2, o, D, F);
    layernorm_kernel<<<M, 256>>>(o, g2, be2);

    split_kernel<<<(M * D / 4 + 255) / 256, 256>>>(o, ah, al, M * D / 4);
    gemm_hmma<false><<<dim3(M / 128, V / 256), 512, GEMM_SMEM>>>(ah, al, wlh, wll, bl, out, V, D);

    softmax_kernel<<<M, 256>>>(out);
}